// round 1
// baseline (speedup 1.0000x reference)
#include <cuda_runtime.h>

// Warping_65094524339056: out[b,x,y,z] = trilinear sample of image at
// (x,y,z) + ddf[b,x,y,z,:], clamped to [0,127].
//
// ddf:   (4,128,128,128,3) fp32  -> d_in[0], 100.7 MB
// image: (4,128,128,128)   fp32  -> d_in[1],  33.5 MB
// out:   (4,128,128,128)   fp32  ->  33.5 MB
//
// Strategy: 4 consecutive z-voxels per thread.
//  - ddf for 4 voxels = 48 bytes = 3x float4 loads (16B aligned).
//  - 4 outputs = 1x float4 store.
//  - 8-corner gather per voxel via __ldg; displacements are small so
//    corners hit L1/L2.

#define DIM 128
#define DMASK 127
#define VOX_PER_THREAD 4

__device__ __forceinline__ float clamp01_127(float v) {
    return fminf(fmaxf(v, 0.0f), 127.0f);
}

__global__ __launch_bounds__(256) void warp_kernel(
    const float* __restrict__ ddf,
    const float* __restrict__ image,
    float* __restrict__ out)
{
    // Each thread handles 4 consecutive voxels along z.
    // Global voxel base index:
    long long t = (long long)blockIdx.x * blockDim.x + threadIdx.x;
    long long vbase = t * VOX_PER_THREAD;             // voxel index of first of 4

    int z0 = (int)(vbase & DMASK);                    // multiple of 4
    int y  = (int)((vbase >> 7)  & DMASK);
    int x  = (int)((vbase >> 14) & DMASK);
    int b  = (int)( vbase >> 21);

    // ddf: 12 floats = 3 x float4, 16B-aligned (48*t bytes)
    const float4* dv = (const float4*)(ddf + vbase * 3);
    float4 q0 = dv[0];
    float4 q1 = dv[1];
    float4 q2 = dv[2];

    // Unpack into per-voxel (dx,dy,dz)
    float dx[4], dy[4], dz[4];
    dx[0]=q0.x; dy[0]=q0.y; dz[0]=q0.z;
    dx[1]=q0.w; dy[1]=q1.x; dz[1]=q1.y;
    dx[2]=q1.z; dy[2]=q1.w; dz[2]=q2.x;
    dx[3]=q2.y; dy[3]=q2.z; dz[3]=q2.w;

    const float* img = image + ((long long)b << 21);

    float res[4];
#pragma unroll
    for (int v = 0; v < 4; v++) {
        float fx = clamp01_127((float)x        + dx[v]);
        float fy = clamp01_127((float)y        + dy[v]);
        float fz = clamp01_127((float)(z0 + v) + dz[v]);

        int ix0 = (int)fx;                 // floor (fx >= 0)
        int iy0 = (int)fy;
        int iz0 = (int)fz;
        float wx = fx - (float)ix0;
        float wy = fy - (float)iy0;
        float wz = fz - (float)iz0;
        int ix1 = min(ix0 + 1, DMASK);
        int iy1 = min(iy0 + 1, DMASK);
        int iz1 = min(iz0 + 1, DMASK);

        int o00 = (ix0 << 14) + (iy0 << 7);
        int o01 = (ix0 << 14) + (iy1 << 7);
        int o10 = (ix1 << 14) + (iy0 << 7);
        int o11 = (ix1 << 14) + (iy1 << 7);

        float v000 = __ldg(img + o00 + iz0);
        float v001 = __ldg(img + o00 + iz1);
        float v010 = __ldg(img + o01 + iz0);
        float v011 = __ldg(img + o01 + iz1);
        float v100 = __ldg(img + o10 + iz0);
        float v101 = __ldg(img + o10 + iz1);
        float v110 = __ldg(img + o11 + iz0);
        float v111 = __ldg(img + o11 + iz1);

        // lerp along z, then y, then x
        float c00 = v000 + wz * (v001 - v000);
        float c01 = v010 + wz * (v011 - v010);
        float c10 = v100 + wz * (v101 - v100);
        float c11 = v110 + wz * (v111 - v110);
        float c0  = c00 + wy * (c01 - c00);
        float c1  = c10 + wy * (c11 - c10);
        res[v]    = c0  + wx * (c1  - c0);
    }

    float4* outv = (float4*)(out + vbase);
    *outv = make_float4(res[0], res[1], res[2], res[3]);
}

extern "C" void kernel_launch(void* const* d_in, const int* in_sizes, int n_in,
                              void* d_out, int out_size)
{
    const float* ddf   = (const float*)d_in[0];
    const float* image = (const float*)d_in[1];
    float* out = (float*)d_out;

    // out_size = 4*128^3 = 8,388,608 voxels; 4 voxels/thread
    long long n_threads = (long long)out_size / VOX_PER_THREAD;  // 2,097,152
    int block = 256;
    int grid = (int)((n_threads + block - 1) / block);           // 8192
    warp_kernel<<<grid, block>>>(ddf, image, out);
}

// round 2
// speedup vs baseline: 1.1810x; 1.1810x over previous
#include <cuda_runtime.h>

// Warping_65094524339056: out[b,x,y,z] = trilinear sample of image at
// (x,y,z) + ddf[b,x,y,z,:], clamped to [0,127].
//
// Round 2: L1TEX-wavefront reduction.
//  - Voxels strided across the warp: lanes cover 32 CONSECUTIVE z, so each
//    gather instruction's lanes that share an (ix,iy) row touch consecutive
//    addresses (1-2 lines per row group instead of 4-5).
//  - z-corner pair (iz0, iz0+1) fetched as one 8B-aligned float2 at
//    (iz0 & ~1); odd iz0 lanes fix up the high element with a predicated
//    scalar load in the same cache line. Halves gather instruction count.

#define DMASK 127
#define VPT 4          // voxels per thread (strided by blockDim)
#define BLOCK 256

__device__ __forceinline__ float clampf(float v) {
    return fminf(fmaxf(v, 0.0f), 127.0f);
}

__global__ __launch_bounds__(BLOCK) void warp_kernel(
    const float* __restrict__ ddf,
    const float* __restrict__ image,
    float* __restrict__ out)
{
    long long chunk = (long long)blockIdx.x * (BLOCK * VPT);
    int tid = threadIdx.x;

#pragma unroll
    for (int v = 0; v < VPT; v++) {
        long long vid = chunk + (long long)v * BLOCK + tid;

        int z = (int)( vid        & DMASK);
        int y = (int)((vid >> 7)  & DMASK);
        int x = (int)((vid >> 14) & DMASK);
        int b = (int)( vid >> 21);

        // ddf: 3 floats, stride-12B across lanes (coalesces to 3 lines/instr)
        const float* dp = ddf + vid * 3;
        float dx = __ldg(dp);
        float dy = __ldg(dp + 1);
        float dz = __ldg(dp + 2);

        float fx = clampf((float)x + dx);
        float fy = clampf((float)y + dy);
        float fz = clampf((float)z + dz);

        int ix0 = (int)fx;
        int iy0 = (int)fy;
        int iz0 = (int)fz;
        float wx = fx - (float)ix0;
        float wy = fy - (float)iy0;
        float wz = fz - (float)iz0;
        int ix1 = min(ix0 + 1, DMASK);
        int iy1 = min(iy0 + 1, DMASK);
        int iz1 = min(iz0 + 1, DMASK);

        const float* img = image + ((long long)b << 21);

        int r00 = (ix0 << 14) + (iy0 << 7);
        int r01 = (ix0 << 14) + (iy1 << 7);
        int r10 = (ix1 << 14) + (iy0 << 7);
        int r11 = (ix1 << 14) + (iy1 << 7);

        int zb  = iz0 & ~1;            // 8B-aligned base
        bool odd = (iz0 & 1);

        // One LDG.64 per (ix,iy) row; predicated LDG.32 fixup for odd iz0.
        float2 a00 = __ldg((const float2*)(img + r00 + zb));
        float2 a01 = __ldg((const float2*)(img + r01 + zb));
        float2 a10 = __ldg((const float2*)(img + r10 + zb));
        float2 a11 = __ldg((const float2*)(img + r11 + zb));

        float lo00 = odd ? a00.y : a00.x;
        float lo01 = odd ? a01.y : a01.x;
        float lo10 = odd ? a10.y : a10.x;
        float lo11 = odd ? a11.y : a11.x;

        float hi00 = a00.y, hi01 = a01.y, hi10 = a10.y, hi11 = a11.y;
        if (odd) {
            // iz1 = iz0+1 = zb+2 (or clamped 127 == zb+1, same line)
            hi00 = __ldg(img + r00 + iz1);
            hi01 = __ldg(img + r01 + iz1);
            hi10 = __ldg(img + r10 + iz1);
            hi11 = __ldg(img + r11 + iz1);
        }

        // lerp z, then y, then x
        float c00 = lo00 + wz * (hi00 - lo00);
        float c01 = lo01 + wz * (hi01 - lo01);
        float c10 = lo10 + wz * (hi10 - lo10);
        float c11 = lo11 + wz * (hi11 - lo11);
        float c0  = c00 + wy * (c01 - c00);
        float c1  = c10 + wy * (c11 - c10);
        out[vid]  = c0  + wx * (c1  - c0);
    }
}

extern "C" void kernel_launch(void* const* d_in, const int* in_sizes, int n_in,
                              void* d_out, int out_size)
{
    const float* ddf   = (const float*)d_in[0];
    const float* image = (const float*)d_in[1];
    float* out = (float*)d_out;

    // out_size = 8,388,608 voxels; 1024 voxels per block
    int grid = (int)((long long)out_size / (BLOCK * VPT));   // 8192
    warp_kernel<<<grid, BLOCK>>>(ddf, image, out);
}